// round 13
// baseline (speedup 1.0000x reference)
#include <cuda_runtime.h>
#include <cuda_fp16.h>
#include <cstdint>

// ---------------------------------------------------------------------------
// R13: 24 warps/SM via 768 threads (8 wm x 3 wn), TILE_E=128, <=85 regs by
//   design (phase-scoped fragments, 4 nt/warp in both GEMMs, GEMM2 split by
//   spatial component i = wn). Same HMMA totals as R8; occ 24% -> 37.5%.
// ---------------------------------------------------------------------------

#define TILE_E 128
#define NTHR   768

__device__ __align__(16) uint32_t g_W1[320*3*32*8];   // 245760
__device__ __align__(16) uint32_t g_W2[256*32*8];     // 65536

// ------------------------- smem layout (bytes) -----------------------------
#define OFF_S1   0        // 128 x 66 half  = 16896
#define OFF_S2   16896    // 128 x 72 half  = 18432
#define OFF_V1   35328    // 3x128 x 34 h   = 26112
#define OFF_V2   61440    // 3x128 x 40 h   = 30720  (ends 92160)
#define OFF_ZSG  92160    // 128 x 98 f32   = 50176  (ends 142336)
#define SMEM_BYTES 142336
// post-GEMM2 aliases (inputs dead after the single sync):
//   zv  [0, 52224)       384 x 34 f32
//   wls [61440, 77824)   64x64 f32
//   wlv [77824, 81920)   32x32 f32
#define OFF_ZV  0
#define OFF_WLS 61440
#define OFF_WLV 77824
#define P_ZV    34

#define P_S1 66
#define P_S2 72
#define P_V1 34
#define P_V2 40

// --------------------------- device helpers --------------------------------
__device__ __forceinline__ void ldm4(uint32_t r[4], const __half* p) {
    uint32_t a = (uint32_t)__cvta_generic_to_shared(p);
    asm volatile("ldmatrix.sync.aligned.m8n8.x4.shared.b16 {%0,%1,%2,%3}, [%4];"
                 : "=r"(r[0]), "=r"(r[1]), "=r"(r[2]), "=r"(r[3]) : "r"(a));
}
__device__ __forceinline__ void mma_f16(float c[4], const uint32_t a[4],
                                        uint32_t b0, uint32_t b1) {
    asm volatile("mma.sync.aligned.m16n8k16.row.col.f32.f16.f16.f32 "
                 "{%0,%1,%2,%3}, {%4,%5,%6,%7}, {%8,%9}, {%0,%1,%2,%3};"
                 : "+f"(c[0]), "+f"(c[1]), "+f"(c[2]), "+f"(c[3])
                 : "r"(a[0]), "r"(a[1]), "r"(a[2]), "r"(a[3]), "r"(b0), "r"(b1));
}
__device__ __forceinline__ uint32_t h2u(__half h) {
    __half2 t = __half2half2(h); return *reinterpret_cast<uint32_t*>(&t);
}
__device__ __forceinline__ uint32_t hmul2u(uint32_t x, uint32_t s) {
    __half2 c = __hmul2(*(__half2*)&x, *(__half2*)&s); return *(uint32_t*)&c;
}
__device__ __forceinline__ uint32_t hfma2u(uint32_t x, uint32_t s, uint32_t a) {
    __half2 c = __hfma2(*(__half2*)&x, *(__half2*)&s, *(__half2*)&a); return *(uint32_t*)&c;
}
__device__ __forceinline__ void loadB8(uint32_t d[8], const uint4* p) {
    uint4 x0 = __ldg(p);
    uint4 x1 = __ldg(p + 1);
    d[0]=x0.x; d[1]=x0.y; d[2]=x0.z; d[3]=x0.w;
    d[4]=x1.x; d[5]=x1.y; d[6]=x1.z; d[7]=x1.w;
}

// ---------------------------------------------------------------------------
// Weight prep. Per-(kt,wn,lane) contiguous 8 uint32 (32B = 2x LDG.128):
//   W1: g_W1[((kt*3+wn)*32+lane)*8 + j], nt=j>>1, r=j&1,
//       n=(wn*4+nt)*8 + lane/4, k0=kt*16+(lane&3)*2+r*8 -> half2{W[k0,n],W[k0+1,n]}
//   W2: g_W2[(kt*32+lane)*8 + j], nt=j>>1, r=j&1, n=nt*8+lane/4.
// ---------------------------------------------------------------------------
__device__ __forceinline__ float w1val(int k, int n,
    const float* wss_s, const float* wvv_s, const float* wss_g, const float* wvv_g) {
    const float A_SS = rsqrtf(8192.0f), A_VV = rsqrtf(6144.0f);
    if (k < 4096) {
        int u = k >> 6, v = k & 63;
        return (n < 64) ? A_SS * wss_s[(u * 64 + v) * 64 + n]
                        : A_SS * wss_g[(u * 64 + v) * 32 + (n - 64)];
    }
    int kk = k - 4096, u = kk >> 5, v = kk & 31;
    return (n < 64) ? A_VV * wvv_s[(u * 32 + v) * 64 + n]
                    : A_VV * wvv_g[(u * 32 + v) * 32 + (n - 64)];
}

__global__ void prep_kernel(const float* __restrict__ wss_s, const float* __restrict__ wvv_s,
                            const float* __restrict__ wss_g, const float* __restrict__ wvv_g,
                            const float* __restrict__ wsv_v, const float* __restrict__ wvs_v) {
    int t = blockIdx.x * blockDim.x + threadIdx.x;
    if (t < 320 * 3 * 32) {
        int lane = t & 31;
        int wn   = (t >> 5) % 3;
        int kt   = t / 96;
        int nb   = lane >> 2;
        int kb   = kt * 16 + (lane & 3) * 2;
#pragma unroll
        for (int j = 0; j < 8; ++j) {
            int nt = j >> 1, r = j & 1;
            int n  = (wn * 4 + nt) * 8 + nb;
            int k0 = kb + r * 8;
            __half2 h = __floats2half2_rn(w1val(k0, n, wss_s, wvv_s, wss_g, wvv_g),
                                          w1val(k0 + 1, n, wss_s, wvv_s, wss_g, wvv_g));
            g_W1[t * 8 + j] = *(uint32_t*)&h;
        }
    } else if (t < 320 * 3 * 32 + 256 * 32) {
        int t2 = t - 320 * 3 * 32;
        int lane = t2 & 31;
        int kt   = t2 >> 5;
        const float A_SV = rsqrtf(12288.0f);
        int nb = lane >> 2;
        int kb = kt * 16 + (lane & 3) * 2;
#pragma unroll
        for (int j = 0; j < 8; ++j) {
            int nt = j >> 1, r = j & 1;
            int n  = nt * 8 + nb;
            float f[2];
#pragma unroll
            for (int q = 0; q < 2; ++q) {
                int k = kb + r * 8 + q;
                if (k < 2048) { int u = k >> 5, v = k & 31; f[q] = A_SV * wsv_v[(u * 32 + v) * 32 + n]; }
                else { int kk = k - 2048, u = kk >> 6, v = kk & 63; f[q] = A_SV * wvs_v[(u * 64 + v) * 32 + n]; }
            }
            __half2 h = __floats2half2_rn(f[0], f[1]);
            g_W2[t2 * 8 + j] = *(uint32_t*)&h;
        }
    }
}

// ---------------------------------------------------------------------------
// Main kernel: 768 threads (24 warps = 8 wm x 3 wn), 128 edges/CTA.
// ---------------------------------------------------------------------------
__global__ void __launch_bounds__(NTHR, 1)
main_kernel(const float* __restrict__ f1, const float* __restrict__ f2,
            const float* __restrict__ wl_s_g, const float* __restrict__ wl_v_g,
            float* __restrict__ out, int E) {
    extern __shared__ char sm[];
    __half* s1h = (__half*)(sm + OFF_S1);
    __half* s2h = (__half*)(sm + OFF_S2);
    __half* v1h = (__half*)(sm + OFF_V1);
    __half* v2h = (__half*)(sm + OFF_V2);
    float*  zsg = (float*)(sm + OFF_ZSG);
    float*  zv  = (float*)(sm + OFF_ZV);
    float*  wls = (float*)(sm + OFF_WLS);
    float*  wlv = (float*)(sm + OFF_WLV);

    const int tid  = threadIdx.x;
    const int warp = tid >> 5;
    const int lane = tid & 31;
    const int wm   = warp & 7;
    const int wn   = warp >> 3;     // 0..2
    const int e0   = blockIdx.x * TILE_E;

    // ---- stage inputs as fp16 (zero-padded past E) ----
    for (int idx = tid; idx < TILE_E * 160; idx += NTHR) {
        int e = idx / 160, c = idx - e * 160;
        float a = 0.f, b = 0.f;
        if (e0 + e < E) {
            a = f1[(size_t)(e0 + e) * 160 + c];
            b = f2[(size_t)(e0 + e) * 160 + c];
        }
        if (c < 64) {
            s1h[e * P_S1 + c] = __float2half_rn(a);
            s2h[e * P_S2 + c] = __float2half_rn(b);
        } else {
            int cc = c - 64, u = cc / 3, i = cc - u * 3;
            v1h[(i * TILE_E + e) * P_V1 + u] = __float2half_rn(a);
            v2h[(i * TILE_E + e) * P_V2 + u] = __float2half_rn(b);
        }
    }
    __syncthreads();

    const int r0 = wm * 16 + (lane >> 2);
    const __half* lm_s2 = s2h + (wm * 16 + (lane & 15)) * P_S2 + ((lane >> 4) << 3);
    const __half* lm_v2 = v2h + (wm * 16 + (lane & 15)) * P_V2 + ((lane >> 4) << 3);

    // =========================== GEMM1 ===========================
    // per-kt stride: 3*32*8 uint32 = 192 uint4; warp base (wn*32+lane)*2 uint4
    const uint4* gB1 = (const uint4*)g_W1 + (size_t)(wn * 32 + lane) * 2;
    float acc1[4][4];
#pragma unroll
    for (int nt = 0; nt < 4; ++nt)
        acc1[nt][0] = acc1[nt][1] = acc1[nt][2] = acc1[nt][3] = 0.f;

    uint32_t Bst[2][8];
    loadB8(Bst[0], gB1);
    loadB8(Bst[1], gB1 + 192);

    // ---- ss phase (c = 0..63): fs2 live ----
    {
        uint32_t fs2[4][4];
#pragma unroll
        for (int j = 0; j < 4; ++j) ldm4(fs2[j], lm_s2 + j * 16);

        for (int c = 0; c < 64; ++c) {
            uint32_t ha = h2u(s1h[r0 * P_S1 + c]);
            uint32_t hb = h2u(s1h[(r0 + 8) * P_S1 + c]);
#pragma unroll
            for (int kl = 0; kl < 4; ++kl) {
                int kt = c * 4 + kl;
                uint32_t* B = Bst[kt & 1];
                uint32_t a[4];
                a[0] = hmul2u(fs2[kl][0], ha); a[1] = hmul2u(fs2[kl][1], hb);
                a[2] = hmul2u(fs2[kl][2], ha); a[3] = hmul2u(fs2[kl][3], hb);
#pragma unroll
                for (int nt = 0; nt < 4; ++nt)
                    mma_f16(acc1[nt], a, B[2 * nt], B[2 * nt + 1]);
                loadB8(B, gB1 + (size_t)(kt + 2) * 192);   // kt+2 <= 321 < 322 rows? guard:
            }
        }
    }
    // NOTE: prefetch above reads up to kt=257+2... ss ends at kt 255; vv continues
    // stream contiguously so kt+2 stays < 322; W1 has 320 kt rows -> clamp needed.
    // (handled below by reloading the first vv buffers explicitly)
    loadB8(Bst[0], gB1 + (size_t)256 * 192);
    loadB8(Bst[1], gB1 + (size_t)257 * 192);

    // ---- vv phase (c = 64..79): fv2 live ----
    {
        uint32_t fv2[3][2][4];
#pragma unroll
        for (int i = 0; i < 3; ++i)
#pragma unroll
            for (int j = 0; j < 2; ++j)
                ldm4(fv2[i][j], lm_v2 + i * (TILE_E * P_V2) + j * 16);

        for (int c = 64; c < 80; ++c) {
            int c2 = c - 64;
#pragma unroll
            for (int h = 0; h < 2; ++h) {
                int u = 2 * c2 + h;
                uint32_t ha[3], hb[3];
#pragma unroll
                for (int i = 0; i < 3; ++i) {
                    ha[i] = h2u(v1h[(i * TILE_E + r0) * P_V1 + u]);
                    hb[i] = h2u(v1h[(i * TILE_E + r0 + 8) * P_V1 + u]);
                }
#pragma unroll
                for (int vb = 0; vb < 2; ++vb) {
                    int kt = c * 4 + h * 2 + vb;
                    uint32_t* B = Bst[kt & 1];
                    uint32_t a[4];
                    a[0] = hmul2u(fv2[0][vb][0], ha[0]);
                    a[1] = hmul2u(fv2[0][vb][1], hb[0]);
                    a[2] = hmul2u(fv2[0][vb][2], ha[0]);
                    a[3] = hmul2u(fv2[0][vb][3], hb[0]);
#pragma unroll
                    for (int i = 1; i < 3; ++i) {
                        a[0] = hfma2u(fv2[i][vb][0], ha[i], a[0]);
                        a[1] = hfma2u(fv2[i][vb][1], hb[i], a[1]);
                        a[2] = hfma2u(fv2[i][vb][2], ha[i], a[2]);
                        a[3] = hfma2u(fv2[i][vb][3], hb[i], a[3]);
                    }
#pragma unroll
                    for (int nt = 0; nt < 4; ++nt)
                        mma_f16(acc1[nt], a, B[2 * nt], B[2 * nt + 1]);
                    int ktn = (kt + 2 < 320) ? kt + 2 : 319;
                    loadB8(B, gB1 + (size_t)ktn * 192);
                }
            }
        }
    }

    // z_sg writeback (fresh region, no sync needed)
    {
        int cb = (lane & 3) * 2;
#pragma unroll
        for (int nt = 0; nt < 4; ++nt) {
            int col = (wn * 4 + nt) * 8 + cb;
            *(float2*)&zsg[r0 * 98 + col]       = make_float2(acc1[nt][0], acc1[nt][1]);
            *(float2*)&zsg[(r0 + 8) * 98 + col] = make_float2(acc1[nt][2], acc1[nt][3]);
        }
    }

    // =========================== GEMM2 (i = wn) ===========================
    // per-kt stride: 32*8 uint32 = 64 uint4; base lane*2
    const uint4* gB2 = (const uint4*)g_W2 + (size_t)lane * 2;
    float acc2[4][4];
#pragma unroll
    for (int nt = 0; nt < 4; ++nt)
        acc2[nt][0] = acc2[nt][1] = acc2[nt][2] = acc2[nt][3] = 0.f;

    uint32_t Cst[2][8];
    loadB8(Cst[0], gB2);
    loadB8(Cst[1], gB2 + 64);

    // ---- sv phase (c = 0..15): X = s1[e,u] * v2[e,v,i=wn] ----
    {
        uint32_t fw[2][4];
#pragma unroll
        for (int vb = 0; vb < 2; ++vb)
            ldm4(fw[vb], lm_v2 + wn * (TILE_E * P_V2) + vb * 16);

        for (int c = 0; c < 16; ++c) {
#pragma unroll
            for (int uu = 0; uu < 4; ++uu) {
                int u = 4 * c + uu;
                uint32_t ha = h2u(s1h[r0 * P_S1 + u]);
                uint32_t hb = h2u(s1h[(r0 + 8) * P_S1 + u]);
#pragma unroll
                for (int vb = 0; vb < 2; ++vb) {
                    int kt = c * 8 + uu * 2 + vb;
                    uint32_t* C = Cst[kt & 1];
                    uint32_t a[4];
                    a[0] = hmul2u(fw[vb][0], ha); a[1] = hmul2u(fw[vb][1], hb);
                    a[2] = hmul2u(fw[vb][2], ha); a[3] = hmul2u(fw[vb][3], hb);
#pragma unroll
                    for (int nt = 0; nt < 4; ++nt)
                        mma_f16(acc2[nt], a, C[2 * nt], C[2 * nt + 1]);
                    loadB8(C, gB2 + (size_t)(kt + 2) * 64);  // kt+2 <= 129 < 256 ok
                }
            }
        }
    }

    // ---- vs phase (c = 16..31): X = v1[e,u,i=wn] * s2[e,v] ----
    {
        uint32_t fs2[4][4];
#pragma unroll
        for (int j = 0; j < 4; ++j) ldm4(fs2[j], lm_s2 + j * 16);

        for (int c = 16; c < 32; ++c) {
            int c2 = c - 16;
#pragma unroll
            for (int h = 0; h < 2; ++h) {
                int u = 2 * c2 + h;
                uint32_t ha = h2u(v1h[(wn * TILE_E + r0) * P_V1 + u]);
                uint32_t hb = h2u(v1h[(wn * TILE_E + r0 + 8) * P_V1 + u]);
#pragma unroll
                for (int vb = 0; vb < 4; ++vb) {
                    int kt = c * 8 + h * 4 + vb;
                    uint32_t* C = Cst[kt & 1];
                    uint32_t a[4];
                    a[0] = hmul2u(fs2[vb][0], ha); a[1] = hmul2u(fs2[vb][1], hb);
                    a[2] = hmul2u(fs2[vb][2], ha); a[3] = hmul2u(fs2[vb][3], hb);
#pragma unroll
                    for (int nt = 0; nt < 4; ++nt)
                        mma_f16(acc2[nt], a, C[2 * nt], C[2 * nt + 1]);
                    int ktn = (kt + 2 < 256) ? kt + 2 : 255;
                    loadB8(C, gB2 + (size_t)ktn * 64);
                }
            }
        }
    }

    __syncthreads();   // all GEMM smem reads done; inputs dead

    // z_v writeback: rows i*128+e, pitch 34 (even -> float2-safe)
    {
        int cb = (lane & 3) * 2;
#pragma unroll
        for (int nt = 0; nt < 4; ++nt) {
            int row = wn * TILE_E + r0;
            int col = nt * 8 + cb;
            *(float2*)&zv[row * P_ZV + col]       = make_float2(acc2[nt][0], acc2[nt][1]);
            *(float2*)&zv[(row + 8) * P_ZV + col] = make_float2(acc2[nt][2], acc2[nt][3]);
        }
    }
    // epilogue weights (disjoint from zv and zsg)
    for (int idx = tid; idx < 4096; idx += NTHR) wls[idx] = wl_s_g[idx];
    for (int idx = tid; idx < 1024; idx += NTHR) wlv[idx] = wl_v_g[idx];

    // activations on z_sg
    for (int idx = tid; idx < TILE_E * 96; idx += NTHR) {
        int e = idx / 96, cc = idx - e * 96;
        float v = zsg[e * 98 + cc];
        float sg = 1.f / (1.f + __expf(-v));
        zsg[e * 98 + cc] = (cc < 64) ? v * sg : sg;
    }
    __syncthreads();

    // gate z_v
    for (int idx = tid; idx < 384 * 32; idx += NTHR) {
        int row = idx >> 5, v = idx & 31;
        int e = row & 127;
        zv[row * P_ZV + v] *= zsg[e * 98 + 64 + v];
    }
    __syncthreads();

    // s_out = silu(z_s) @ wl_s / 8   (threads 0..511)
    if (tid < 512) {
        int e = tid >> 2, wbase = (tid & 3) * 16;
        bool valid = (e0 + e) < E;
#pragma unroll
        for (int wb = 0; wb < 16; wb += 8) {
            float a[8];
#pragma unroll
            for (int j = 0; j < 8; ++j) a[j] = 0.f;
            for (int u = 0; u < 64; ++u) {
                float zs = zsg[e * 98 + u];
                float4 w0 = *(const float4*)&wls[u * 64 + wbase + wb];
                float4 w1 = *(const float4*)&wls[u * 64 + wbase + wb + 4];
                a[0] += zs * w0.x; a[1] += zs * w0.y; a[2] += zs * w0.z; a[3] += zs * w0.w;
                a[4] += zs * w1.x; a[5] += zs * w1.y; a[6] += zs * w1.z; a[7] += zs * w1.w;
            }
            if (valid) {
                float4 o0 = make_float4(a[0]*0.125f, a[1]*0.125f, a[2]*0.125f, a[3]*0.125f);
                float4 o1 = make_float4(a[4]*0.125f, a[5]*0.125f, a[6]*0.125f, a[7]*0.125f);
                *(float4*)&out[(size_t)(e0 + e) * 160 + wbase + wb]     = o0;
                *(float4*)&out[(size_t)(e0 + e) * 160 + wbase + wb + 4] = o1;
            }
        }
    }
    // v_out = (g*z_v) @ wl_v / sqrt(32)  (threads 512..767 + wrap: use strided)
    const float R32 = 0.17677669529663687f;
    for (int r = tid; r < 384; r += NTHR) {
        int i = r >> 7, e = r & 127;
        float acc[32];
#pragma unroll
        for (int w = 0; w < 32; ++w) acc[w] = 0.f;
        for (int v = 0; v < 32; ++v) {
            float zval = zv[r * P_ZV + v];
#pragma unroll
            for (int w4 = 0; w4 < 32; w4 += 4) {
                float4 wv = *(const float4*)&wlv[v * 32 + w4];
                acc[w4]   += zval * wv.x; acc[w4+1] += zval * wv.y;
                acc[w4+2] += zval * wv.z; acc[w4+3] += zval * wv.w;
            }
        }
        if (e0 + e < E) {
#pragma unroll
            for (int w = 0; w < 32; ++w)
                out[(size_t)(e0 + e) * 160 + 64 + w * 3 + i] = acc[w] * R32;
        }
    }
}

// ---------------------------------------------------------------------------
extern "C" void kernel_launch(void* const* d_in, const int* in_sizes, int n_in,
                              void* d_out, int out_size) {
    const float* f1    = (const float*)d_in[0];
    const float* f2    = (const float*)d_in[1];
    const float* wss_s = (const float*)d_in[4];
    const float* wvv_s = (const float*)d_in[5];
    const float* wss_g = (const float*)d_in[6];
    const float* wvv_g = (const float*)d_in[7];
    const float* wsv_v = (const float*)d_in[8];
    const float* wvs_v = (const float*)d_in[9];
    const float* wl_s  = (const float*)d_in[10];
    const float* wl_v  = (const float*)d_in[11];
    float* out = (float*)d_out;
    int E = in_sizes[0] / 160;

    prep_kernel<<<152, 256>>>(wss_s, wvv_s, wss_g, wvv_g, wsv_v, wvs_v);
    cudaFuncSetAttribute(main_kernel, cudaFuncAttributeMaxDynamicSharedMemorySize, SMEM_BYTES);
    int ntiles = (E + TILE_E - 1) / TILE_E;
    main_kernel<<<ntiles, NTHR, SMEM_BYTES>>>(f1, f2, wl_s, wl_v, out, E);
}

// round 14
// speedup vs baseline: 1.1882x; 1.1882x over previous
#include <cuda_runtime.h>
#include <cuda_fp16.h>
#include <cstdint>

// ---------------------------------------------------------------------------
// R14: R8 structure (512 thr, 8 wm x 2 wn, M=16/warp) + per-warp cp.async
//   B pipeline: depth-4 private smem ring per warp, commit/wait_group only
//   (no CTA barriers). B path becomes LDGSTS->LDS instead of latency-exposed
//   LDG; register double-buffer removed (regs freed for ring bookkeeping).
// ---------------------------------------------------------------------------

#define TILE_E 128
#define NTHR   512

__device__ __align__(16) uint32_t g_W1[320*2*3*128];   // per (kt,wn): 1536 B
__device__ __align__(16) uint32_t g_W2[256*2*128];     // per (kt,wn): 512 B

// ------------------------- smem layout (bytes) -----------------------------
#define OFF_S1   0        // 128 x 66 half  = 16896
#define OFF_V1   16896    // 3x128 x 34 h   = 26112   (ends 43008)
#define OFF_S2   43008    // 128 x 72 half  = 18432
#define OFF_V2   61440    // 3x128 x 40 h   = 30720   (ends 92160)
#define OFF_RING 92160    // 16 warps x 6144 = 98304  (ends 190464)
#define SMEM_BYTES 190464
// aliases:
//   zsg [43008, 92160)  128 x 96 f32 = 49152  (s2h/v2h dead after frag hoist)
//   zv  [92160, 144384) 384 x 34 f32 = 52224  (ring dead post-GEMM2)
//   wls [144384, 160768), wlv [160768, 164864)
#define OFF_ZSG  43008
#define P_ZSG    96
#define OFF_ZV   92160
#define P_ZV     34
#define OFF_WLS  144384
#define OFF_WLV  160768

#define P_S1 66
#define P_S2 72
#define P_V1 34
#define P_V2 40

// --------------------------- device helpers --------------------------------
__device__ __forceinline__ void ldm4(uint32_t r[4], const __half* p) {
    uint32_t a = (uint32_t)__cvta_generic_to_shared(p);
    asm volatile("ldmatrix.sync.aligned.m8n8.x4.shared.b16 {%0,%1,%2,%3}, [%4];"
                 : "=r"(r[0]), "=r"(r[1]), "=r"(r[2]), "=r"(r[3]) : "r"(a));
}
__device__ __forceinline__ void mma_f16(float c[4], const uint32_t a[4],
                                        uint32_t b0, uint32_t b1) {
    asm volatile("mma.sync.aligned.m16n8k16.row.col.f32.f16.f16.f32 "
                 "{%0,%1,%2,%3}, {%4,%5,%6,%7}, {%8,%9}, {%0,%1,%2,%3};"
                 : "+f"(c[0]), "+f"(c[1]), "+f"(c[2]), "+f"(c[3])
                 : "r"(a[0]), "r"(a[1]), "r"(a[2]), "r"(a[3]), "r"(b0), "r"(b1));
}
__device__ __forceinline__ uint32_t h2u(__half h) {
    __half2 t = __half2half2(h); return *reinterpret_cast<uint32_t*>(&t);
}
__device__ __forceinline__ uint32_t hmul2u(uint32_t x, uint32_t s) {
    __half2 c = __hmul2(*(__half2*)&x, *(__half2*)&s); return *(uint32_t*)&c;
}
__device__ __forceinline__ uint32_t hfma2u(uint32_t x, uint32_t s, uint32_t a) {
    __half2 c = __hfma2(*(__half2*)&x, *(__half2*)&s, *(__half2*)&a); return *(uint32_t*)&c;
}
__device__ __forceinline__ void cp16(uint32_t d, const void* s) {
    asm volatile("cp.async.cg.shared.global [%0], [%1], 16;" :: "r"(d), "l"(s));
}
#define CP_COMMIT() asm volatile("cp.async.commit_group;" ::: "memory")
#define CP_WAIT3()  asm volatile("cp.async.wait_group 3;" ::: "memory")
#define CP_WAIT0()  asm volatile("cp.async.wait_group 0;" ::: "memory")

__device__ __forceinline__ void lds12(uint32_t d[12], uint32_t a) {
    asm volatile("ld.shared.v4.u32 {%0,%1,%2,%3}, [%4];"
                 : "=r"(d[0]), "=r"(d[1]), "=r"(d[2]), "=r"(d[3]) : "r"(a));
    asm volatile("ld.shared.v4.u32 {%0,%1,%2,%3}, [%4];"
                 : "=r"(d[4]), "=r"(d[5]), "=r"(d[6]), "=r"(d[7]) : "r"(a + 512));
    asm volatile("ld.shared.v4.u32 {%0,%1,%2,%3}, [%4];"
                 : "=r"(d[8]), "=r"(d[9]), "=r"(d[10]), "=r"(d[11]) : "r"(a + 1024));
}
__device__ __forceinline__ void lds4(uint32_t d[4], uint32_t a) {
    asm volatile("ld.shared.v4.u32 {%0,%1,%2,%3}, [%4];"
                 : "=r"(d[0]), "=r"(d[1]), "=r"(d[2]), "=r"(d[3]) : "r"(a));
}

// ---------------------------------------------------------------------------
// Weight prep (identical packing to R8).
// ---------------------------------------------------------------------------
__global__ void prep_kernel(const float* __restrict__ wss_s, const float* __restrict__ wvv_s,
                            const float* __restrict__ wss_g, const float* __restrict__ wvv_g,
                            const float* __restrict__ wsv_v, const float* __restrict__ wvs_v) {
    int t = blockIdx.x * blockDim.x + threadIdx.x;
    const float A_SS = rsqrtf(8192.0f);
    const float A_VV = rsqrtf(6144.0f);
    const float A_SV = rsqrtf(12288.0f);

    if (t < 320 * 2 * 3 * 32) {
        int lane = t & 31;
        int g    = (t >> 5) % 3;
        int wn   = (t / 96) & 1;
        int kt   = t / 192;
#pragma unroll
        for (int j = 0; j < 4; ++j) {
            int flatr = g * 4 + j;
            int nt = wn * 6 + (flatr >> 1);
            int r  = flatr & 1;
            int n  = nt * 8 + (lane >> 2);
            float f[2];
#pragma unroll
            for (int q = 0; q < 2; ++q) {
                int k = kt * 16 + (lane & 3) * 2 + r * 8 + q;
                float val;
                if (k < 4096) {
                    int u = k >> 6, v = k & 63;
                    val = (n < 64) ? A_SS * wss_s[(u * 64 + v) * 64 + n]
                                   : A_SS * wss_g[(u * 64 + v) * 32 + (n - 64)];
                } else {
                    int kk = k - 4096, u = kk >> 5, v = kk & 31;
                    val = (n < 64) ? A_VV * wvv_s[(u * 32 + v) * 64 + n]
                                   : A_VV * wvv_g[(u * 32 + v) * 32 + (n - 64)];
                }
                f[q] = val;
            }
            __half2 h = __floats2half2_rn(f[0], f[1]);
            g_W1[((kt * 2 + wn) * 3 + g) * 128 + lane * 4 + j] = *(uint32_t*)&h;
        }
    } else if (t < 320 * 2 * 3 * 32 + 256 * 2 * 32) {
        int t2 = t - 320 * 2 * 3 * 32;
        int lane = t2 & 31;
        int wn   = (t2 >> 5) & 1;
        int kt   = t2 >> 6;
#pragma unroll
        for (int j = 0; j < 4; ++j) {
            int nt = wn * 2 + (j >> 1);
            int r  = j & 1;
            int n  = nt * 8 + (lane >> 2);
            float f[2];
#pragma unroll
            for (int q = 0; q < 2; ++q) {
                int k = kt * 16 + (lane & 3) * 2 + r * 8 + q;
                float val;
                if (k < 2048) { int u = k >> 5, v = k & 31; val = A_SV * wsv_v[(u * 32 + v) * 32 + n]; }
                else { int kk = k - 2048, u = kk >> 6, v = kk & 63; val = A_SV * wvs_v[(u * 64 + v) * 32 + n]; }
                f[q] = val;
            }
            __half2 h = __floats2half2_rn(f[0], f[1]);
            g_W2[(kt * 2 + wn) * 128 + lane * 4 + j] = *(uint32_t*)&h;
        }
    }
}

// ---------------------------------------------------------------------------
// Main kernel: 512 threads (16 warps = 8 wm x 2 wn), 128 edges/CTA.
// Per-warp depth-4 cp.async B ring; no CTA barriers in mainloops.
// ---------------------------------------------------------------------------
__global__ void __launch_bounds__(NTHR, 1)
main_kernel(const float* __restrict__ f1, const float* __restrict__ f2,
            const float* __restrict__ wl_s_g, const float* __restrict__ wl_v_g,
            float* __restrict__ out, int E) {
    extern __shared__ char sm[];
    __half* s1h = (__half*)(sm + OFF_S1);
    __half* v1h = (__half*)(sm + OFF_V1);
    __half* s2h = (__half*)(sm + OFF_S2);
    __half* v2h = (__half*)(sm + OFF_V2);
    float*  zsg = (float*)(sm + OFF_ZSG);
    float*  zv  = (float*)(sm + OFF_ZV);
    float*  wls = (float*)(sm + OFF_WLS);
    float*  wlv = (float*)(sm + OFF_WLV);
    const uint32_t smb = (uint32_t)__cvta_generic_to_shared(sm);

    const int tid  = threadIdx.x;
    const int warp = tid >> 5;
    const int lane = tid & 31;
    const int wm   = warp & 7;
    const int wn   = warp >> 3;
    const int e0   = blockIdx.x * TILE_E;

    // ---- stage inputs as fp16 (zero-padded past E) ----
    for (int idx = tid; idx < TILE_E * 160; idx += NTHR) {
        int e = idx / 160, c = idx - e * 160;
        float a = 0.f, b = 0.f;
        if (e0 + e < E) {
            a = f1[(size_t)(e0 + e) * 160 + c];
            b = f2[(size_t)(e0 + e) * 160 + c];
        }
        if (c < 64) {
            s1h[e * P_S1 + c] = __float2half_rn(a);
            s2h[e * P_S2 + c] = __float2half_rn(b);
        } else {
            int cc = c - 64, u = cc / 3, i = cc - u * 3;
            v1h[(i * TILE_E + e) * P_V1 + u] = __float2half_rn(a);
            v2h[(i * TILE_E + e) * P_V2 + u] = __float2half_rn(b);
        }
    }
    __syncthreads();

    const int r0 = wm * 16 + (lane >> 2);
    const __half* lm_s2 = s2h + (wm * 16 + (lane & 15)) * P_S2 + ((lane >> 4) << 3);
    const __half* lm_v2 = v2h + (wm * 16 + (lane & 15)) * P_V2 + ((lane >> 4) << 3);

    // hoisted A-side fragments (held through both GEMMs; s2h/v2h dead after)
    uint32_t fs2[4][4];
    uint32_t fv2[3][2][4];
#pragma unroll
    for (int j = 0; j < 4; ++j) ldm4(fs2[j], lm_s2 + j * 16);
#pragma unroll
    for (int i = 0; i < 3; ++i)
#pragma unroll
        for (int j = 0; j < 2; ++j)
            ldm4(fv2[i][j], lm_v2 + i * (TILE_E * P_V2) + j * 16);
    __syncthreads();   // all warps done reading s2h/v2h; zsg may overwrite

    const uint32_t ringW = smb + OFF_RING + (uint32_t)warp * 6144 + (uint32_t)lane * 16;
    const char* W1s = (const char*)g_W1 + (size_t)wn * 1536 + (size_t)lane * 16;
    const char* W2s = (const char*)g_W2 + (size_t)wn * 512  + (size_t)lane * 16;

    // =========================== GEMM1 ===========================
    float acc1[6][4];
#pragma unroll
    for (int nt = 0; nt < 6; ++nt)
        acc1[nt][0] = acc1[nt][1] = acc1[nt][2] = acc1[nt][3] = 0.f;

    // prologue: fill 4 ring slots (1536 B each)
#pragma unroll
    for (int p = 0; p < 4; ++p) {
        const char* s = W1s + (size_t)p * 3072;
        uint32_t d = ringW + p * 1536;
        cp16(d, s); cp16(d + 512, s + 512); cp16(d + 1024, s + 1024);
        CP_COMMIT();
    }

    for (int c = 0; c < 80; ++c) {
        if (c < 64) {                       // ss: X = s1[e,u=c] * s2[e,v]
            uint32_t ha = h2u(s1h[r0 * P_S1 + c]);
            uint32_t hb = h2u(s1h[(r0 + 8) * P_S1 + c]);
#pragma unroll
            for (int kl = 0; kl < 4; ++kl) {
                int kt = c * 4 + kl;
                CP_WAIT3();
                uint32_t B[12];
                lds12(B, ringW + (uint32_t)(kt & 3) * 1536);
                uint32_t a[4];
                a[0] = hmul2u(fs2[kl][0], ha); a[1] = hmul2u(fs2[kl][1], hb);
                a[2] = hmul2u(fs2[kl][2], ha); a[3] = hmul2u(fs2[kl][3], hb);
#pragma unroll
                for (int nt = 0; nt < 6; ++nt)
                    mma_f16(acc1[nt], a, B[2 * nt], B[2 * nt + 1]);
                int ktn = kt + 4;
                if (ktn < 320) {
                    const char* s = W1s + (size_t)ktn * 3072;
                    uint32_t d = ringW + (uint32_t)(ktn & 3) * 1536;
                    cp16(d, s); cp16(d + 512, s + 512); cp16(d + 1024, s + 1024);
                }
                CP_COMMIT();
            }
        } else {                            // vv: X = sum_i v1[e,u,i]*v2[e,v,i]
            int c2 = c - 64;
#pragma unroll
            for (int h = 0; h < 2; ++h) {
                int u = 2 * c2 + h;
                uint32_t ha[3], hb[3];
#pragma unroll
                for (int i = 0; i < 3; ++i) {
                    ha[i] = h2u(v1h[(i * TILE_E + r0) * P_V1 + u]);
                    hb[i] = h2u(v1h[(i * TILE_E + r0 + 8) * P_V1 + u]);
                }
#pragma unroll
                for (int vb = 0; vb < 2; ++vb) {
                    int kt = c * 4 + h * 2 + vb;
                    CP_WAIT3();
                    uint32_t B[12];
                    lds12(B, ringW + (uint32_t)(kt & 3) * 1536);
                    uint32_t a[4];
                    a[0] = hmul2u(fv2[0][vb][0], ha[0]);
                    a[1] = hmul2u(fv2[0][vb][1], hb[0]);
                    a[2] = hmul2u(fv2[0][vb][2], ha[0]);
                    a[3] = hmul2u(fv2[0][vb][3], hb[0]);
#pragma unroll
                    for (int i = 1; i < 3; ++i) {
                        a[0] = hfma2u(fv2[i][vb][0], ha[i], a[0]);
                        a[1] = hfma2u(fv2[i][vb][1], hb[i], a[1]);
                        a[2] = hfma2u(fv2[i][vb][2], ha[i], a[2]);
                        a[3] = hfma2u(fv2[i][vb][3], hb[i], a[3]);
                    }
#pragma unroll
                    for (int nt = 0; nt < 6; ++nt)
                        mma_f16(acc1[nt], a, B[2 * nt], B[2 * nt + 1]);
                    int ktn = kt + 4;
                    if (ktn < 320) {
                        const char* s = W1s + (size_t)ktn * 3072;
                        uint32_t d = ringW + (uint32_t)(ktn & 3) * 1536;
                        cp16(d, s); cp16(d + 512, s + 512); cp16(d + 1024, s + 1024);
                    }
                    CP_COMMIT();
                }
            }
        }
    }

    // z_sg writeback (pitch 96; region disjoint from s1h/v1h; no barrier)
    {
        int cb = (lane & 3) * 2;
#pragma unroll
        for (int nt = 0; nt < 6; ++nt) {
            int col = (wn * 6 + nt) * 8 + cb;
            *(float2*)&zsg[r0 * P_ZSG + col]       = make_float2(acc1[nt][0], acc1[nt][1]);
            *(float2*)&zsg[(r0 + 8) * P_ZSG + col] = make_float2(acc1[nt][2], acc1[nt][3]);
        }
    }

    // =========================== GEMM2 ===========================
    CP_WAIT0();
    float acc2[3][2][4];
#pragma unroll
    for (int i = 0; i < 3; ++i)
#pragma unroll
        for (int nt = 0; nt < 2; ++nt)
            acc2[i][nt][0] = acc2[i][nt][1] = acc2[i][nt][2] = acc2[i][nt][3] = 0.f;

    // prologue: 4 slots of 512 B
#pragma unroll
    for (int p = 0; p < 4; ++p) {
        cp16(ringW + p * 512, W2s + (size_t)p * 1024);
        CP_COMMIT();
    }

    for (int c = 0; c < 32; ++c) {
        if (c < 16) {                       // X = s1[e,u] * v2[e,v,i]
#pragma unroll
            for (int uu = 0; uu < 4; ++uu) {
                int u = 4 * c + uu;
                uint32_t ha = h2u(s1h[r0 * P_S1 + u]);
                uint32_t hb = h2u(s1h[(r0 + 8) * P_S1 + u]);
#pragma unroll
                for (int vb = 0; vb < 2; ++vb) {
                    int kt = c * 8 + uu * 2 + vb;
                    CP_WAIT3();
                    uint32_t C[4];
                    lds4(C, ringW + (uint32_t)(kt & 3) * 512);
                    uint32_t ai[3][4];
#pragma unroll
                    for (int i = 0; i < 3; ++i) {
                        ai[i][0] = hmul2u(fv2[i][vb][0], ha);
                        ai[i][1] = hmul2u(fv2[i][vb][1], hb);
                        ai[i][2] = hmul2u(fv2[i][vb][2], ha);
                        ai[i][3] = hmul2u(fv2[i][vb][3], hb);
                    }
#pragma unroll
                    for (int nt = 0; nt < 2; ++nt) {
#pragma unroll
                        for (int i = 0; i < 3; ++i)
                            mma_f16(acc2[i][nt], ai[i], C[2 * nt], C[2 * nt + 1]);
                    }
                    int ktn = kt + 4;
                    if (ktn < 256)
                        cp16(ringW + (uint32_t)(ktn & 3) * 512, W2s + (size_t)ktn * 1024);
                    CP_COMMIT();
                }
            }
        } else {                            // X = v1[e,u,i] * s2[e,v]
            int c2 = c - 16;
#pragma unroll
            for (int h = 0; h < 2; ++h) {
                int u = 2 * c2 + h;
                uint32_t ha[3], hb[3];
#pragma unroll
                for (int i = 0; i < 3; ++i) {
                    ha[i] = h2u(v1h[(i * TILE_E + r0) * P_V1 + u]);
                    hb[i] = h2u(v1h[(i * TILE_E + r0 + 8) * P_V1 + u]);
                }
#pragma unroll
                for (int vb = 0; vb < 4; ++vb) {
                    int kt = c * 8 + h * 4 + vb;
                    CP_WAIT3();
                    uint32_t C[4];
                    lds4(C, ringW + (uint32_t)(kt & 3) * 512);
                    uint32_t ai[3][4];
#pragma unroll
                    for (int i = 0; i < 3; ++i) {
                        ai[i][0] = hmul2u(fs2[vb][0], ha[i]);
                        ai[i][1] = hmul2u(fs2[vb][1], hb[i]);
                        ai[i][2] = hmul2u(fs2[vb][2], ha[i]);
                        ai[i][3] = hmul2u(fs2[vb][3], hb[i]);
                    }
#pragma unroll
                    for (int nt = 0; nt < 2; ++nt) {
#pragma unroll
                        for (int i = 0; i < 3; ++i)
                            mma_f16(acc2[i][nt], ai[i], C[2 * nt], C[2 * nt + 1]);
                    }
                    int ktn = kt + 4;
                    if (ktn < 256)
                        cp16(ringW + (uint32_t)(ktn & 3) * 512, W2s + (size_t)ktn * 1024);
                    CP_COMMIT();
                }
            }
        }
    }
    CP_WAIT0();

    __syncthreads();   // everyone done with ring + zsg complete

    // z_v writeback into ring region (dead); pitch 34 (even, float2-safe)
    {
        int cb = (lane & 3) * 2;
#pragma unroll
        for (int i = 0; i < 3; ++i)
#pragma unroll
            for (int nt = 0; nt < 2; ++nt) {
                int row = i * TILE_E + r0;
                int col = (wn * 2 + nt) * 8 + cb;
                *(float2*)&zv[row * P_ZV + col]       = make_float2(acc2[i][nt][0], acc2[i][nt][1]);
                *(float2*)&zv[(row + 8) * P_ZV + col] = make_float2(acc2[i][nt][2], acc2[i][nt][3]);
            }
    }
    // epilogue weights (disjoint regions in dead ring area)
    for (int idx = tid; idx < 4096; idx += NTHR) wls[idx] = wl_s_g[idx];
    for (int idx = tid; idx < 1024; idx += NTHR) wlv[idx] = wl_v_g[idx];

    // activations on z_sg
    for (int idx = tid; idx < TILE_E * 96; idx += NTHR) {
        int e = idx / 96, cc = idx - e * 96;
        float v = zsg[e * P_ZSG + cc];
        float sg = 1.f / (1.f + __expf(-v));
        zsg[e * P_ZSG + cc] = (cc < 64) ? v * sg : sg;
    }
    __syncthreads();

    // gate z_v
    for (int idx = tid; idx < 384 * 32; idx += NTHR) {
        int row = idx >> 5, v = idx & 31;
        int e = row & 127;
        zv[row * P_ZV + v] *= zsg[e * P_ZSG + 64 + v];
    }
    __syncthreads();

    // s_out = silu(z_s) @ wl_s / 8
    {
        int e = tid >> 2, wbase = (tid & 3) * 16;
        bool valid = (e0 + e) < E;
#pragma unroll
        for (int wb = 0; wb < 16; wb += 8) {
            float a[8];
#pragma unroll
            for (int j = 0; j < 8; ++j) a[j] = 0.f;
            for (int u = 0; u < 64; ++u) {
                float zs = zsg[e * P_ZSG + u];
                float4 w0 = *(const float4*)&wls[u * 64 + wbase + wb];
                float4 w1 = *(const float4*)&wls[u * 64 + wbase + wb + 4];
                a[0] += zs * w0.x; a[1] += zs * w0.y; a[2] += zs * w0.z; a[3] += zs * w0.w;
                a[4] += zs * w1.x; a[5] += zs * w1.y; a[6] += zs * w1.z; a[7] += zs * w1.w;
            }
            if (valid) {
                float4 o0 = make_float4(a[0]*0.125f, a[1]*0.125f, a[2]*0.125f, a[3]*0.125f);
                float4 o1 = make_float4(a[4]*0.125f, a[5]*0.125f, a[6]*0.125f, a[7]*0.125f);
                *(float4*)&out[(size_t)(e0 + e) * 160 + wbase + wb]     = o0;
                *(float4*)&out[(size_t)(e0 + e) * 160 + wbase + wb + 4] = o1;
            }
        }
    }
    // v_out = (g*z_v) @ wl_v / sqrt(32)
    const float R32 = 0.17677669529663687f;
    for (int r = tid; r < 384; r += NTHR) {
        int i = r >> 7, e = r & 127;
        float acc[32];
#pragma unroll
        for (int w = 0; w < 32; ++w) acc[w] = 0.f;
        for (int v = 0; v < 32; ++v) {
            float zval = zv[r * P_ZV + v];
#pragma unroll
            for (int w4 = 0; w4 < 32; w4 += 4) {
                float4 wv = *(const float4*)&wlv[v * 32 + w4];
                acc[w4]   += zval * wv.x; acc[w4+1] += zval * wv.y;
                acc[w4+2] += zval * wv.z; acc[w4+3] += zval * wv.w;
            }
        }
        if (e0 + e < E) {
#pragma unroll
            for (int w = 0; w < 32; ++w)
                out[(size_t)(e0 + e) * 160 + 64 + w * 3 + i] = acc[w] * R32;
        }
    }
}

// ---------------------------------------------------------------------------
extern "C" void kernel_launch(void* const* d_in, const int* in_sizes, int n_in,
                              void* d_out, int out_size) {
    const float* f1    = (const float*)d_in[0];
    const float* f2    = (const float*)d_in[1];
    const float* wss_s = (const float*)d_in[4];
    const float* wvv_s = (const float*)d_in[5];
    const float* wss_g = (const float*)d_in[6];
    const float* wvv_g = (const float*)d_in[7];
    const float* wsv_v = (const float*)d_in[8];
    const float* wvs_v = (const float*)d_in[9];
    const float* wl_s  = (const float*)d_in[10];
    const float* wl_v  = (const float*)d_in[11];
    float* out = (float*)d_out;
    int E = in_sizes[0] / 160;

    prep_kernel<<<304, 256>>>(wss_s, wvv_s, wss_g, wvv_g, wsv_v, wvs_v);
    cudaFuncSetAttribute(main_kernel, cudaFuncAttributeMaxDynamicSharedMemorySize, SMEM_BYTES);
    int ntiles = (E + TILE_E - 1) / TILE_E;
    main_kernel<<<ntiles, NTHR, SMEM_BYTES>>>(f1, f2, wl_s, wl_v, out, E);
}

// round 15
// speedup vs baseline: 1.4347x; 1.2074x over previous
#include <cuda_runtime.h>
#include <cuda_fp16.h>
#include <cstdint>

// ---------------------------------------------------------------------------
// R15: R8 structure (512 thr, 8 wm x 2 wn, TILE_E=128) + depth-4 register
//   B prefetch (covers L2 latency), funded by phase-scoped A-fragments.
//   Scalar LDS prefetched one iteration ahead in ss / sv phases.
// ---------------------------------------------------------------------------

#define TILE_E 128
#define NTHR   512

__device__ __align__(16) uint32_t g_W1[320*2*3*128];   // 245760
__device__ __align__(16) uint32_t g_W2[256*2*128];     // 65536

// ------------------------- smem layout (bytes) -----------------------------
#define OFF_S1   0        // 128 x 66 half   = 16896
#define OFF_S2   16896    // 128 x 72 half   = 18432
#define OFF_V1   35328    // 3x128 x 34 h    = 26112
#define OFF_V2   61440    // 3x128 x 40 h    = 30720  (ends 92160)
#define OFF_ZSG  92160    // 128 x 98 f32    = 50176
#define SMEM_BYTES 142336
// post-GEMM2 aliases: zv (384x34 f32 = 52224) at 0 (inputs dead),
//                     wls (16384) at OFF_V2, wlv (4096) at OFF_V2+16384
#define OFF_ZV   0
#define P_ZV     34
#define OFF_WLS  61440
#define OFF_WLV  77824

#define P_S1 66
#define P_S2 72
#define P_V1 34
#define P_V2 40

// --------------------------- device helpers --------------------------------
__device__ __forceinline__ void ldm4(uint32_t r[4], const __half* p) {
    uint32_t a = (uint32_t)__cvta_generic_to_shared(p);
    asm volatile("ldmatrix.sync.aligned.m8n8.x4.shared.b16 {%0,%1,%2,%3}, [%4];"
                 : "=r"(r[0]), "=r"(r[1]), "=r"(r[2]), "=r"(r[3]) : "r"(a));
}
__device__ __forceinline__ void mma_f16(float c[4], const uint32_t a[4],
                                        uint32_t b0, uint32_t b1) {
    asm volatile("mma.sync.aligned.m16n8k16.row.col.f32.f16.f16.f32 "
                 "{%0,%1,%2,%3}, {%4,%5,%6,%7}, {%8,%9}, {%0,%1,%2,%3};"
                 : "+f"(c[0]), "+f"(c[1]), "+f"(c[2]), "+f"(c[3])
                 : "r"(a[0]), "r"(a[1]), "r"(a[2]), "r"(a[3]), "r"(b0), "r"(b1));
}
__device__ __forceinline__ uint32_t h2u(__half h) {
    __half2 t = __half2half2(h); return *reinterpret_cast<uint32_t*>(&t);
}
__device__ __forceinline__ uint32_t hmul2u(uint32_t x, uint32_t s) {
    __half2 c = __hmul2(*(__half2*)&x, *(__half2*)&s); return *(uint32_t*)&c;
}
__device__ __forceinline__ uint32_t hfma2u(uint32_t x, uint32_t s, uint32_t a) {
    __half2 c = __hfma2(*(__half2*)&x, *(__half2*)&s, *(__half2*)&a); return *(uint32_t*)&c;
}
__device__ __forceinline__ void loadB12(uint32_t d[12], const uint4* p) {
    uint4 x0 = __ldg(p);
    uint4 x1 = __ldg(p + 32);
    uint4 x2 = __ldg(p + 64);
    d[0]=x0.x; d[1]=x0.y; d[2]=x0.z;  d[3]=x0.w;
    d[4]=x1.x; d[5]=x1.y; d[6]=x1.z;  d[7]=x1.w;
    d[8]=x2.x; d[9]=x2.y; d[10]=x2.z; d[11]=x2.w;
}
__device__ __forceinline__ void loadB4(uint32_t d[4], const uint4* p) {
    uint4 x0 = __ldg(p);
    d[0]=x0.x; d[1]=x0.y; d[2]=x0.z; d[3]=x0.w;
}

// ---------------------------------------------------------------------------
// Weight prep (identical to R8 packing).
// ---------------------------------------------------------------------------
__global__ void prep_kernel(const float* __restrict__ wss_s, const float* __restrict__ wvv_s,
                            const float* __restrict__ wss_g, const float* __restrict__ wvv_g,
                            const float* __restrict__ wsv_v, const float* __restrict__ wvs_v) {
    int t = blockIdx.x * blockDim.x + threadIdx.x;
    const float A_SS = rsqrtf(8192.0f);
    const float A_VV = rsqrtf(6144.0f);
    const float A_SV = rsqrtf(12288.0f);

    if (t < 320 * 2 * 3 * 32) {
        int lane = t & 31;
        int g    = (t >> 5) % 3;
        int wn   = (t / 96) & 1;
        int kt   = t / 192;
#pragma unroll
        for (int j = 0; j < 4; ++j) {
            int flatr = g * 4 + j;
            int nt = wn * 6 + (flatr >> 1);
            int r  = flatr & 1;
            int n  = nt * 8 + (lane >> 2);
            float f[2];
#pragma unroll
            for (int q = 0; q < 2; ++q) {
                int k = kt * 16 + (lane & 3) * 2 + r * 8 + q;
                float val;
                if (k < 4096) {
                    int u = k >> 6, v = k & 63;
                    val = (n < 64) ? A_SS * wss_s[(u * 64 + v) * 64 + n]
                                   : A_SS * wss_g[(u * 64 + v) * 32 + (n - 64)];
                } else {
                    int kk = k - 4096, u = kk >> 5, v = kk & 31;
                    val = (n < 64) ? A_VV * wvv_s[(u * 32 + v) * 64 + n]
                                   : A_VV * wvv_g[(u * 32 + v) * 32 + (n - 64)];
                }
                f[q] = val;
            }
            __half2 h = __floats2half2_rn(f[0], f[1]);
            g_W1[((kt * 2 + wn) * 3 + g) * 128 + lane * 4 + j] = *(uint32_t*)&h;
        }
    } else if (t < 320 * 2 * 3 * 32 + 256 * 2 * 32) {
        int t2 = t - 320 * 2 * 3 * 32;
        int lane = t2 & 31;
        int wn   = (t2 >> 5) & 1;
        int kt   = t2 >> 6;
#pragma unroll
        for (int j = 0; j < 4; ++j) {
            int nt = wn * 2 + (j >> 1);
            int r  = j & 1;
            int n  = nt * 8 + (lane >> 2);
            float f[2];
#pragma unroll
            for (int q = 0; q < 2; ++q) {
                int k = kt * 16 + (lane & 3) * 2 + r * 8 + q;
                float val;
                if (k < 2048) { int u = k >> 5, v = k & 31; val = A_SV * wsv_v[(u * 32 + v) * 32 + n]; }
                else { int kk = k - 2048, u = kk >> 6, v = kk & 63; val = A_SV * wvs_v[(u * 64 + v) * 32 + n]; }
                f[q] = val;
            }
            __half2 h = __floats2half2_rn(f[0], f[1]);
            g_W2[(kt * 2 + wn) * 128 + lane * 4 + j] = *(uint32_t*)&h;
        }
    }
}

// ---------------------------------------------------------------------------
// Main kernel: 512 threads (16 warps = 8 wm x 2 wn), 128 edges/CTA.
// ---------------------------------------------------------------------------
__global__ void __launch_bounds__(NTHR, 1)
main_kernel(const float* __restrict__ f1, const float* __restrict__ f2,
            const float* __restrict__ wl_s_g, const float* __restrict__ wl_v_g,
            float* __restrict__ out, int E) {
    extern __shared__ char sm[];
    __half* s1h = (__half*)(sm + OFF_S1);
    __half* s2h = (__half*)(sm + OFF_S2);
    __half* v1h = (__half*)(sm + OFF_V1);
    __half* v2h = (__half*)(sm + OFF_V2);
    float*  zsg = (float*)(sm + OFF_ZSG);
    float*  zv  = (float*)(sm + OFF_ZV);
    float*  wls = (float*)(sm + OFF_WLS);
    float*  wlv = (float*)(sm + OFF_WLV);

    const int tid  = threadIdx.x;
    const int warp = tid >> 5;
    const int lane = tid & 31;
    const int wm   = warp & 7;
    const int wn   = warp >> 3;
    const int e0   = blockIdx.x * TILE_E;

    // ---- stage inputs as fp16 (zero-padded past E) ----
    for (int idx = tid; idx < TILE_E * 160; idx += NTHR) {
        int e = idx / 160, c = idx - e * 160;
        float a = 0.f, b = 0.f;
        if (e0 + e < E) {
            a = f1[(size_t)(e0 + e) * 160 + c];
            b = f2[(size_t)(e0 + e) * 160 + c];
        }
        if (c < 64) {
            s1h[e * P_S1 + c] = __float2half_rn(a);
            s2h[e * P_S2 + c] = __float2half_rn(b);
        } else {
            int cc = c - 64, u = cc / 3, i = cc - u * 3;
            v1h[(i * TILE_E + e) * P_V1 + u] = __float2half_rn(a);
            v2h[(i * TILE_E + e) * P_V2 + u] = __float2half_rn(b);
        }
    }
    __syncthreads();

    const int r0 = wm * 16 + (lane >> 2);
    const __half* lm_s2 = s2h + (wm * 16 + (lane & 15)) * P_S2 + ((lane >> 4) << 3);
    const __half* lm_v2 = v2h + (wm * 16 + (lane & 15)) * P_V2 + ((lane >> 4) << 3);

    // =========================== GEMM1 ===========================
    const uint4* gB1 = (const uint4*)g_W1 + (size_t)wn * 96 + lane;
    float acc1[6][4];
#pragma unroll
    for (int nt = 0; nt < 6; ++nt)
        acc1[nt][0] = acc1[nt][1] = acc1[nt][2] = acc1[nt][3] = 0.f;

    uint32_t Bst[4][12];
#pragma unroll
    for (int p = 0; p < 4; ++p) loadB12(Bst[p], gB1 + (size_t)p * 192);

    // ---- ss phase (kt 0..255): fs2 live, scalars prefetched ----
    {
        uint32_t fs2[4][4];
#pragma unroll
        for (int j = 0; j < 4; ++j) ldm4(fs2[j], lm_s2 + j * 16);

        uint32_t ha = h2u(s1h[r0 * P_S1]);
        uint32_t hb = h2u(s1h[(r0 + 8) * P_S1]);
        for (int c = 0; c < 64; ++c) {
            uint32_t han = ha, hbn = hb;
            if (c + 1 < 64) {
                han = h2u(s1h[r0 * P_S1 + c + 1]);
                hbn = h2u(s1h[(r0 + 8) * P_S1 + c + 1]);
            }
#pragma unroll
            for (int kl = 0; kl < 4; ++kl) {
                int kt = c * 4 + kl;
                uint32_t* B = Bst[kl];          // kt & 3 == kl (static)
                uint32_t a[4];
                a[0] = hmul2u(fs2[kl][0], ha); a[1] = hmul2u(fs2[kl][1], hb);
                a[2] = hmul2u(fs2[kl][2], ha); a[3] = hmul2u(fs2[kl][3], hb);
#pragma unroll
                for (int nt = 0; nt < 6; ++nt)
                    mma_f16(acc1[nt], a, B[2 * nt], B[2 * nt + 1]);
                int ktn = kt + 4;
                if (ktn < 320) loadB12(B, gB1 + (size_t)ktn * 192);
            }
            ha = han; hb = hbn;
        }
    }

    // ---- vv phase (kt 256..319): fv2 live ----
    {
        uint32_t fv2[3][2][4];
#pragma unroll
        for (int i = 0; i < 3; ++i)
#pragma unroll
            for (int j = 0; j < 2; ++j)
                ldm4(fv2[i][j], lm_v2 + i * (TILE_E * P_V2) + j * 16);

        for (int c = 64; c < 80; ++c) {
            int c2 = c - 64;
#pragma unroll
            for (int h = 0; h < 2; ++h) {
                int u = 2 * c2 + h;
                uint32_t ha[3], hb[3];
#pragma unroll
                for (int i = 0; i < 3; ++i) {
                    ha[i] = h2u(v1h[(i * TILE_E + r0) * P_V1 + u]);
                    hb[i] = h2u(v1h[(i * TILE_E + r0 + 8) * P_V1 + u]);
                }
#pragma unroll
                for (int vb = 0; vb < 2; ++vb) {
                    int kt = c * 4 + h * 2 + vb;
                    uint32_t* B = Bst[h * 2 + vb];   // kt & 3 static
                    uint32_t a[4];
                    a[0] = hmul2u(fv2[0][vb][0], ha[0]);
                    a[1] = hmul2u(fv2[0][vb][1], hb[0]);
                    a[2] = hmul2u(fv2[0][vb][2], ha[0]);
                    a[3] = hmul2u(fv2[0][vb][3], hb[0]);
#pragma unroll
                    for (int i = 1; i < 3; ++i) {
                        a[0] = hfma2u(fv2[i][vb][0], ha[i], a[0]);
                        a[1] = hfma2u(fv2[i][vb][1], hb[i], a[1]);
                        a[2] = hfma2u(fv2[i][vb][2], ha[i], a[2]);
                        a[3] = hfma2u(fv2[i][vb][3], hb[i], a[3]);
                    }
#pragma unroll
                    for (int nt = 0; nt < 6; ++nt)
                        mma_f16(acc1[nt], a, B[2 * nt], B[2 * nt + 1]);
                    int ktn = kt + 4;
                    if (ktn < 320) loadB12(B, gB1 + (size_t)ktn * 192);
                }
            }
        }
    }

    // z_sg writeback (separate region; no barrier needed)
    {
        int cb = (lane & 3) * 2;
#pragma unroll
        for (int nt = 0; nt < 6; ++nt) {
            int col = (wn * 6 + nt) * 8 + cb;
            *(float2*)&zsg[r0 * 98 + col]       = make_float2(acc1[nt][0], acc1[nt][1]);
            *(float2*)&zsg[(r0 + 8) * 98 + col] = make_float2(acc1[nt][2], acc1[nt][3]);
        }
    }

    // =========================== GEMM2 ===========================
    const uint4* gB2 = (const uint4*)g_W2 + (size_t)wn * 32 + lane;
    float acc2[3][2][4];
#pragma unroll
    for (int i = 0; i < 3; ++i)
#pragma unroll
        for (int nt = 0; nt < 2; ++nt)
            acc2[i][nt][0] = acc2[i][nt][1] = acc2[i][nt][2] = acc2[i][nt][3] = 0.f;

    uint32_t Cst[4][4];
#pragma unroll
    for (int p = 0; p < 4; ++p) loadB4(Cst[p], gB2 + (size_t)p * 64);

    // ---- sv phase (kt 0..127): fv2 live, scalars prefetched ----
    {
        uint32_t fv2[3][2][4];
#pragma unroll
        for (int i = 0; i < 3; ++i)
#pragma unroll
            for (int j = 0; j < 2; ++j)
                ldm4(fv2[i][j], lm_v2 + i * (TILE_E * P_V2) + j * 16);

        uint32_t ha = h2u(s1h[r0 * P_S1]);
        uint32_t hb = h2u(s1h[(r0 + 8) * P_S1]);
        for (int c = 0; c < 16; ++c) {
#pragma unroll
            for (int uu = 0; uu < 4; ++uu) {
                int u = 4 * c + uu;
                uint32_t han = ha, hbn = hb;
                if (u + 1 < 64) {
                    han = h2u(s1h[r0 * P_S1 + u + 1]);
                    hbn = h2u(s1h[(r0 + 8) * P_S1 + u + 1]);
                }
#pragma unroll
                for (int vb = 0; vb < 2; ++vb) {
                    int kt = c * 8 + uu * 2 + vb;
                    uint32_t* C = Cst[(uu * 2 + vb) & 3];  // kt & 3 static
                    uint32_t ai[3][4];
#pragma unroll
                    for (int i = 0; i < 3; ++i) {
                        ai[i][0] = hmul2u(fv2[i][vb][0], ha);
                        ai[i][1] = hmul2u(fv2[i][vb][1], hb);
                        ai[i][2] = hmul2u(fv2[i][vb][2], ha);
                        ai[i][3] = hmul2u(fv2[i][vb][3], hb);
                    }
#pragma unroll
                    for (int nt = 0; nt < 2; ++nt) {
#pragma unroll
                        for (int i = 0; i < 3; ++i)
                            mma_f16(acc2[i][nt], ai[i], C[2 * nt], C[2 * nt + 1]);
                    }
                    int ktn = kt + 4;
                    if (ktn < 256) loadB4(C, gB2 + (size_t)ktn * 64);
                }
                ha = han; hb = hbn;
            }
        }
    }

    // ---- vs phase (kt 128..255): fs2 reloaded ----
    {
        uint32_t fs2[4][4];
#pragma unroll
        for (int j = 0; j < 4; ++j) ldm4(fs2[j], lm_s2 + j * 16);

        for (int c = 16; c < 32; ++c) {
            int c2 = c - 16;
#pragma unroll
            for (int h = 0; h < 2; ++h) {
                int u = 2 * c2 + h;
                uint32_t ha[3], hb[3];
#pragma unroll
                for (int i = 0; i < 3; ++i) {
                    ha[i] = h2u(v1h[(i * TILE_E + r0) * P_V1 + u]);
                    hb[i] = h2u(v1h[(i * TILE_E + r0 + 8) * P_V1 + u]);
                }
#pragma unroll
                for (int vb = 0; vb < 4; ++vb) {
                    int kt = c * 8 + h * 4 + vb;
                    uint32_t* C = Cst[vb];           // kt & 3 == vb (static)
                    uint32_t ai[3][4];
#pragma unroll
                    for (int i = 0; i < 3; ++i) {
                        ai[i][0] = hmul2u(fs2[vb][0], ha[i]);
                        ai[i][1] = hmul2u(fs2[vb][1], hb[i]);
                        ai[i][2] = hmul2u(fs2[vb][2], ha[i]);
                        ai[i][3] = hmul2u(fs2[vb][3], hb[i]);
                    }
#pragma unroll
                    for (int nt = 0; nt < 2; ++nt) {
#pragma unroll
                        for (int i = 0; i < 3; ++i)
                            mma_f16(acc2[i][nt], ai[i], C[2 * nt], C[2 * nt + 1]);
                    }
                    int ktn = kt + 4;
                    if (ktn < 256) loadB4(C, gB2 + (size_t)ktn * 64);
                }
            }
        }
    }

    __syncthreads();   // all GEMM smem reads done; inputs dead

    // z_v writeback (aliases input head; pitch 34 even -> float2-safe)
    {
        int cb = (lane & 3) * 2;
#pragma unroll
        for (int i = 0; i < 3; ++i)
#pragma unroll
            for (int nt = 0; nt < 2; ++nt) {
                int row = i * TILE_E + r0;
                int col = (wn * 2 + nt) * 8 + cb;
                *(float2*)&zv[row * P_ZV + col]       = make_float2(acc2[i][nt][0], acc2[i][nt][1]);
                *(float2*)&zv[(row + 8) * P_ZV + col] = make_float2(acc2[i][nt][2], acc2[i][nt][3]);
            }
    }
    // epilogue weights into dead v2h region (post-GEMM2; read after next sync)
    for (int idx = tid; idx < 4096; idx += NTHR) wls[idx] = wl_s_g[idx];
    for (int idx = tid; idx < 1024; idx += NTHR) wlv[idx] = wl_v_g[idx];

    // activations on z_sg
    for (int idx = tid; idx < TILE_E * 96; idx += NTHR) {
        int e = idx / 96, cc = idx - e * 96;
        float v = zsg[e * 98 + cc];
        float sg = 1.f / (1.f + __expf(-v));
        zsg[e * 98 + cc] = (cc < 64) ? v * sg : sg;
    }
    __syncthreads();

    // gate z_v
    for (int idx = tid; idx < 384 * 32; idx += NTHR) {
        int row = idx >> 5, v = idx & 31;
        int e = row & 127;
        zv[row * P_ZV + v] *= zsg[e * 98 + 64 + v];
    }
    __syncthreads();

    // s_out = silu(z_s) @ wl_s / 8
    {
        int e = tid >> 2, wbase = (tid & 3) * 16;
        bool valid = (e0 + e) < E;
#pragma unroll
        for (int wb = 0; wb < 16; wb += 8) {
            float a[8];
#pragma unroll
            for (int j = 0; j < 8; ++j) a[j] = 0.f;
            for (int u = 0; u < 64; ++u) {
                float zs = zsg[e * 98 + u];
                float4 w0 = *(const float4*)&wls[u * 64 + wbase + wb];
                float4 w1 = *(const float4*)&wls[u * 64 + wbase + wb + 4];
                a[0] += zs * w0.x; a[1] += zs * w0.y; a[2] += zs * w0.z; a[3] += zs * w0.w;
                a[4] += zs * w1.x; a[5] += zs * w1.y; a[6] += zs * w1.z; a[7] += zs * w1.w;
            }
            if (valid) {
                float4 o0 = make_float4(a[0]*0.125f, a[1]*0.125f, a[2]*0.125f, a[3]*0.125f);
                float4 o1 = make_float4(a[4]*0.125f, a[5]*0.125f, a[6]*0.125f, a[7]*0.125f);
                *(float4*)&out[(size_t)(e0 + e) * 160 + wbase + wb]     = o0;
                *(float4*)&out[(size_t)(e0 + e) * 160 + wbase + wb + 4] = o1;
            }
        }
    }
    // v_out = (g*z_v) @ wl_v / sqrt(32)
    const float R32 = 0.17677669529663687f;
    for (int r = tid; r < 384; r += NTHR) {
        int i = r >> 7, e = r & 127;
        float acc[32];
#pragma unroll
        for (int w = 0; w < 32; ++w) acc[w] = 0.f;
        for (int v = 0; v < 32; ++v) {
            float zval = zv[r * P_ZV + v];
#pragma unroll
            for (int w4 = 0; w4 < 32; w4 += 4) {
                float4 wv = *(const float4*)&wlv[v * 32 + w4];
                acc[w4]   += zval * wv.x; acc[w4+1] += zval * wv.y;
                acc[w4+2] += zval * wv.z; acc[w4+3] += zval * wv.w;
            }
        }
        if (e0 + e < E) {
#pragma unroll
            for (int w = 0; w < 32; ++w)
                out[(size_t)(e0 + e) * 160 + 64 + w * 3 + i] = acc[w] * R32;
        }
    }
}

// ---------------------------------------------------------------------------
extern "C" void kernel_launch(void* const* d_in, const int* in_sizes, int n_in,
                              void* d_out, int out_size) {
    const float* f1    = (const float*)d_in[0];
    const float* f2    = (const float*)d_in[1];
    const float* wss_s = (const float*)d_in[4];
    const float* wvv_s = (const float*)d_in[5];
    const float* wss_g = (const float*)d_in[6];
    const float* wvv_g = (const float*)d_in[7];
    const float* wsv_v = (const float*)d_in[8];
    const float* wvs_v = (const float*)d_in[9];
    const float* wl_s  = (const float*)d_in[10];
    const float* wl_v  = (const float*)d_in[11];
    float* out = (float*)d_out;
    int E = in_sizes[0] / 160;

    prep_kernel<<<304, 256>>>(wss_s, wvv_s, wss_g, wvv_g, wsv_v, wvs_v);
    cudaFuncSetAttribute(main_kernel, cudaFuncAttributeMaxDynamicSharedMemorySize, SMEM_BYTES);
    int ntiles = (E + TILE_E - 1) / TILE_E;
    main_kernel<<<ntiles, NTHR, SMEM_BYTES>>>(f1, f2, wl_s, wl_v, out, E);
}